// round 14
// baseline (speedup 1.0000x reference)
#include <cuda_runtime.h>
#include <cuda_bf16.h>
#include <cstdint>

// SpikingLayer: inputs = X @ W^T, then LIF scan — fused, with scan blocks
// INTERLEAVED into the dispatch order so they overlap the GEMM.
//
// Constraints learned:
//  R6/R7: the LIF threshold demands the reference's sequential-k fp32 FMA chain
//         bitwise (any k-reorder -> spike flips -> rel_err ~1.3e-3 FAIL).
//  R2:    sequential SIMT fp32 GEMM = rel_err 0.0, at the FFMA issue roofline.
//  R11:   FFMA2 is an issue-slot saver, not a FLOP doubler -> regressed.
//  R12:   appending scan blocks after 4000 GEMM blocks = zero overlap (they
//         only become resident in the last wave). DRAM is 5.8% idle during the
//         GEMM -> the scan's 786MB can ride along for free IF co-resident.
//
// This round: batch b's two scan blocks sit at blockIdx P(b) = 8*(my_hi(b)+1)+2b,
// i.e. immediately after the last GEMM tile covering rows [500b, 500b+500).
// They spin briefly on a per-batch tile counter, then scan while later GEMM
// tiles compute. All waited-on tiles are earlier in dispatch order -> no deadlock.
// d_out = U [128,500,1024] ++ S [128,500,1024] (S region doubles as GEMM scratch).

static constexpr int M_ = 64000;   // 128*500
static constexpr int N_ = 1024;
static constexpr int K_ = 700;
static constexpr int B_ = 128;
static constexpr int T_ = 500;
static constexpr int H_ = 1024;

static constexpr int GEMM_BLOCKS = (M_ / 128) * (N_ / 128);  // 4000
static constexpr int SCAN_BLOCKS = 2 * B_;                   // 256
static constexpr int TOTAL_BLOCKS = GEMM_BLOCKS + SCAN_BLOCKS;

__device__ int g_cnt[B_];   // per-batch GEMM-tile arrival counters

__global__ void zero_cnt_kernel() {
    if (threadIdx.x < B_) g_cnt[threadIdx.x] = 0;
}

// ---------------------------------------------------------------------------
// Fused kernel with interleaved roles.
// ---------------------------------------------------------------------------
__global__ void __launch_bounds__(256) fused_kernel(
    const float* __restrict__ A,   // X  [M_, K_]
    const float* __restrict__ W,   // W  [N_, K_]
    float* __restrict__ U,         // [B_, T_, H_]
    float* S)                      // [B_, T_, H_] : GEMM C output, then spikes in-place
{
    const int id = blockIdx.x;
    const int tid = threadIdx.x;

    // ---- role resolution: scan pair for batch b lives at P(b), P(b)+1 ----
    int scan_b = -1, scan_half = 0, nprev = 0;
    #pragma unroll 4
    for (int b = 0; b < B_; b++) {
        const int my_hi = (T_ * b + T_ - 1) >> 7;        // last m-tile of batch b
        const int P = ((my_hi + 1) << 3) + 2 * b;        // final index of pair start
        if (id == P)     { scan_b = b; scan_half = 0; }
        if (id == P + 1) { scan_b = b; scan_half = 1; }
        if (P + 2 <= id) nprev++;                        // pair fully before id
    }

    if (scan_b < 0) {
        // ================= GEMM role (bitwise-identical to R2) ==============
        const int g = id - 2 * nprev;    // 0..3999
        __shared__ float As[8][128];
        __shared__ float Bs[8][128];

        const int my = g >> 3;           // 0..499
        const int nx = g & 7;            // 0..7
        const int bm = my * 128;
        const int bn = nx * 128;

        const int lr = tid >> 1;         // 0..127
        const int lk = (tid & 1) * 4;    // 0 or 4
        const float* Aptr = A + (size_t)(bm + lr) * K_ + lk;
        const float* Wptr = W + (size_t)(bn + lr) * K_ + lk;

        const int ty = tid >> 4;         // rows ty*8..ty*8+7
        const int tx = tid & 15;         // cols tx*8..tx*8+7

        float acc[8][8];
        #pragma unroll
        for (int i = 0; i < 8; i++)
            #pragma unroll
            for (int j = 0; j < 8; j++) acc[i][j] = 0.0f;

        for (int k0 = 0; k0 < K_; k0 += 8) {
            float4 av, bv;
            if (k0 + lk + 4 <= K_) {   // only tail chunk (k0=696, lk=4) fails
                av = *reinterpret_cast<const float4*>(Aptr + k0);
                bv = *reinterpret_cast<const float4*>(Wptr + k0);
            } else {
                av = make_float4(0.f, 0.f, 0.f, 0.f);
                bv = make_float4(0.f, 0.f, 0.f, 0.f);
            }
            __syncthreads();
            As[lk + 0][lr] = av.x; As[lk + 1][lr] = av.y;
            As[lk + 2][lr] = av.z; As[lk + 3][lr] = av.w;
            Bs[lk + 0][lr] = bv.x; Bs[lk + 1][lr] = bv.y;
            Bs[lk + 2][lr] = bv.z; Bs[lk + 3][lr] = bv.w;
            __syncthreads();

            #pragma unroll
            for (int kk = 0; kk < 8; kk++) {
                float ar[8], br[8];
                *reinterpret_cast<float4*>(&ar[0]) =
                    *reinterpret_cast<const float4*>(&As[kk][ty * 8]);
                *reinterpret_cast<float4*>(&ar[4]) =
                    *reinterpret_cast<const float4*>(&As[kk][ty * 8 + 4]);
                *reinterpret_cast<float4*>(&br[0]) =
                    *reinterpret_cast<const float4*>(&Bs[kk][tx * 8]);
                *reinterpret_cast<float4*>(&br[4]) =
                    *reinterpret_cast<const float4*>(&Bs[kk][tx * 8 + 4]);
                #pragma unroll
                for (int i = 0; i < 8; i++)
                    #pragma unroll
                    for (int j = 0; j < 8; j++)
                        acc[i][j] = fmaf(ar[i], br[j], acc[i][j]);
            }
        }

        // epilogue into S (the inputs scratch region)
        #pragma unroll
        for (int i = 0; i < 8; i++) {
            float* crow = S + (size_t)(bm + ty * 8 + i) * N_ + bn + tx * 8;
            *reinterpret_cast<float4*>(crow) =
                make_float4(acc[i][0], acc[i][1], acc[i][2], acc[i][3]);
            *reinterpret_cast<float4*>(crow + 4) =
                make_float4(acc[i][4], acc[i][5], acc[i][6], acc[i][7]);
        }

        // publish: stores visible, then bump every batch this tile touches
        __threadfence();
        __syncthreads();
        if (tid == 0) {
            const int b_lo = bm / T_;
            const int b_hi = (bm + 127) / T_;
            for (int b = b_lo; b <= b_hi; b++)
                atomicAdd(&g_cnt[b], 1);
        }
    } else {
        // ================= scan role =======================================
        const int b = scan_b;

        if (tid == 0) {
            const int my_lo = (b * T_) >> 7;
            const int my_hi = (b * T_ + T_ - 1) >> 7;
            const int target = (my_hi - my_lo + 1) * 8;
            while (atomicAdd(&g_cnt[b], 0) < target) __nanosleep(256);
            __threadfence();
        }
        __syncthreads();

        const float PHI = 0.36787944117144233f;   // exp(-1)
        const float GAM = 0.81873075307798182f;   // exp(-0.2)
        const float BET = 0.90483741803595952f;   // exp(-0.1)
        const int P2 = H_ / 2;                    // 512 float2 per (b,t)

        float2* Uv = reinterpret_cast<float2*>(U);
        float2* Sv = reinterpret_cast<float2*>(S);
        const int h = scan_half * 256 + tid;      // 0..511
        const size_t base = (size_t)b * T_ * P2 + h;
        float2* Up = Uv + base;
        float2* Sp = Sv + base;

        float2 buf[8];
        #pragma unroll
        for (int i = 0; i < 8; i++) buf[i] = Sp[(size_t)i * P2];

        Up[0] = make_float2(0.f, 0.f);
        Sp[0] = make_float2(0.f, 0.f);

        float Hx = 0.f, Ix = 0.f, Ux = 0.f, Sx = 0.f;
        float Hy = 0.f, Iy = 0.f, Uy = 0.f, Sy = 0.f;

        for (int t0 = 1; t0 < T_; t0 += 8) {
            #pragma unroll
            for (int u = 0; u < 8; u++) {
                const int t = t0 + u;
                if (t < T_) {
                    const float2 inp = buf[u];                         // inputs[t-1]
                    if (t + 7 < T_) buf[u] = Sp[(size_t)(t + 7) * P2]; // prefetch
                    const float Hnx = fmaf(PHI, Hx, inp.x);
                    const float Inx = fmaf(GAM, Ix, Hx);
                    const float Unx = BET * (Ux - Ix) - Sx;
                    const float Snx = (Unx > 1.f) ? 1.f : 0.f;
                    const float Hny = fmaf(PHI, Hy, inp.y);
                    const float Iny = fmaf(GAM, Iy, Hy);
                    const float Uny = BET * (Uy - Iy) - Sy;
                    const float Sny = (Uny > 1.f) ? 1.f : 0.f;
                    Up[(size_t)t * P2] = make_float2(Unx, Uny);
                    Sp[(size_t)t * P2] = make_float2(Snx, Sny);
                    Hx = Hnx; Ix = Inx; Ux = Unx; Sx = Snx;
                    Hy = Hny; Iy = Iny; Uy = Uny; Sy = Sny;
                }
            }
        }
    }
}

// ---------------------------------------------------------------------------
extern "C" void kernel_launch(void* const* d_in, const int* in_sizes, int n_in,
                              void* d_out, int out_size) {
    const float* X = (const float*)d_in[0];   // [128, 500, 700]
    const float* W = (const float*)d_in[1];   // [1024, 700]
    float* outU = (float*)d_out;              // [128, 500, 1024]
    float* outS = outU + (size_t)M_ * N_;     // [128, 500, 1024]

    zero_cnt_kernel<<<1, 128>>>();
    fused_kernel<<<TOTAL_BLOCKS, 256>>>(X, W, outU, outS);
}

// round 15
// speedup vs baseline: 1.1274x; 1.1274x over previous
#include <cuda_runtime.h>
#include <cuda_bf16.h>
#include <cstdint>

// SpikingLayer: inputs = X @ W^T, then LIF scan — fused with ZERO dedicated
// scan blocks: the last GEMM tile to finish for batch b runs batch b's scan.
//
// Constraints learned:
//  R6/R7: LIF threshold demands the reference's sequential-k fp32 FMA chain
//         bitwise (any reorder -> spike flips -> rel_err ~1.3e-3 FAIL).
//  R2:    sequential SIMT fp32 GEMM = rel_err 0.0, at the FFMA issue roofline.
//  R12:   appended scan blocks = zero overlap (resident only in last wave).
//  R14:   interleaved scan blocks spin a full wave before their tiles COMPLETE
//         (~6% slots dead) + per-block role loop -> regression.
//  => overlap must cost no slots and no spinning: tile-triggered scanning.
//
// d_out = U [128,500,1024] ++ S [128,500,1024] (S region doubles as GEMM scratch).

static constexpr int M_ = 64000;   // 128*500
static constexpr int N_ = 1024;
static constexpr int K_ = 700;
static constexpr int B_ = 128;
static constexpr int T_ = 500;
static constexpr int H_ = 1024;

static constexpr int GEMM_BLOCKS = (M_ / 128) * (N_ / 128);  // 4000

__device__ int g_cnt[B_];   // per-batch GEMM-tile completion counters

__global__ void zero_cnt_kernel() {
    if (threadIdx.x < B_) g_cnt[threadIdx.x] = 0;
}

// ---------------------------------------------------------------------------
// LIF scan for one batch, run by one 256-thread block: 4 neurons per thread
// (float4), in-place over the S region (read-ahead by 7 -> WAR safe).
// H[t]=PHI*H[t-1]+inp[t-1]; I[t]=GAMMA*I[t-1]+H[t-1];
// U[t]=BETA*(U[t-1]-I[t-1])-S[t-1]; S[t]=(U[t]>1).
// ---------------------------------------------------------------------------
__device__ __forceinline__ void scan_batch(int b, int tid, float* U, float* S) {
    const float PHI = 0.36787944117144233f;   // exp(-1)
    const float GAM = 0.81873075307798182f;   // exp(-0.2)
    const float BET = 0.90483741803595952f;   // exp(-0.1)
    const int P4 = H_ / 4;                    // 256 float4 per (b,t)

    float4* Up = reinterpret_cast<float4*>(U) + (size_t)b * T_ * P4 + tid;
    float4* Sp = reinterpret_cast<float4*>(S) + (size_t)b * T_ * P4 + tid;

    float4 buf[8];
    #pragma unroll
    for (int i = 0; i < 8; i++) buf[i] = Sp[(size_t)i * P4];

    Up[0] = make_float4(0.f, 0.f, 0.f, 0.f);
    Sp[0] = make_float4(0.f, 0.f, 0.f, 0.f);

    float Hs[4] = {0.f, 0.f, 0.f, 0.f};
    float Is[4] = {0.f, 0.f, 0.f, 0.f};
    float Us[4] = {0.f, 0.f, 0.f, 0.f};
    float Ss[4] = {0.f, 0.f, 0.f, 0.f};

    for (int t0 = 1; t0 < T_; t0 += 8) {
        #pragma unroll
        for (int u = 0; u < 8; u++) {
            const int t = t0 + u;
            if (t < T_) {
                const float4 inp = buf[u];                         // inputs[t-1]
                if (t + 7 < T_) buf[u] = Sp[(size_t)(t + 7) * P4]; // prefetch
                const float in_[4] = {inp.x, inp.y, inp.z, inp.w};
                float Un[4], Sn[4];
                #pragma unroll
                for (int q = 0; q < 4; q++) {
                    const float Hn = fmaf(PHI, Hs[q], in_[q]);
                    const float In = fmaf(GAM, Is[q], Hs[q]);
                    Un[q] = BET * (Us[q] - Is[q]) - Ss[q];
                    Sn[q] = (Un[q] > 1.f) ? 1.f : 0.f;
                    Hs[q] = Hn; Is[q] = In; Us[q] = Un[q]; Ss[q] = Sn[q];
                }
                Up[(size_t)t * P4] = make_float4(Un[0], Un[1], Un[2], Un[3]);
                Sp[(size_t)t * P4] = make_float4(Sn[0], Sn[1], Sn[2], Sn[3]);
            }
        }
    }
}

// ---------------------------------------------------------------------------
// Fused kernel: pure R2 GEMM grid; last tile per batch triggers that batch's scan.
// ---------------------------------------------------------------------------
__global__ void __launch_bounds__(256) fused_kernel(
    const float* __restrict__ A,   // X  [M_, K_]
    const float* __restrict__ W,   // W  [N_, K_]
    float* __restrict__ U,         // [B_, T_, H_]
    float* S)                      // [B_, T_, H_] : GEMM C output, then spikes in-place
{
    const int id = blockIdx.x;
    const int tid = threadIdx.x;

    // ================= GEMM (bitwise-identical to round 2) ==================
    __shared__ float As[8][128];
    __shared__ float Bs[8][128];

    const int my = id >> 3;          // 0..499
    const int nx = id & 7;           // 0..7
    const int bm = my * 128;
    const int bn = nx * 128;

    const int lr = tid >> 1;         // 0..127
    const int lk = (tid & 1) * 4;    // 0 or 4
    const float* Aptr = A + (size_t)(bm + lr) * K_ + lk;
    const float* Wptr = W + (size_t)(bn + lr) * K_ + lk;

    const int ty = tid >> 4;         // rows ty*8..ty*8+7
    const int tx = tid & 15;         // cols tx*8..tx*8+7

    float acc[8][8];
    #pragma unroll
    for (int i = 0; i < 8; i++)
        #pragma unroll
        for (int j = 0; j < 8; j++) acc[i][j] = 0.0f;

    for (int k0 = 0; k0 < K_; k0 += 8) {
        float4 av, bv;
        if (k0 + lk + 4 <= K_) {   // only tail chunk (k0=696, lk=4) fails
            av = *reinterpret_cast<const float4*>(Aptr + k0);
            bv = *reinterpret_cast<const float4*>(Wptr + k0);
        } else {
            av = make_float4(0.f, 0.f, 0.f, 0.f);
            bv = make_float4(0.f, 0.f, 0.f, 0.f);
        }
        __syncthreads();
        As[lk + 0][lr] = av.x; As[lk + 1][lr] = av.y;
        As[lk + 2][lr] = av.z; As[lk + 3][lr] = av.w;
        Bs[lk + 0][lr] = bv.x; Bs[lk + 1][lr] = bv.y;
        Bs[lk + 2][lr] = bv.z; Bs[lk + 3][lr] = bv.w;
        __syncthreads();

        #pragma unroll
        for (int kk = 0; kk < 8; kk++) {
            float ar[8], br[8];
            *reinterpret_cast<float4*>(&ar[0]) =
                *reinterpret_cast<const float4*>(&As[kk][ty * 8]);
            *reinterpret_cast<float4*>(&ar[4]) =
                *reinterpret_cast<const float4*>(&As[kk][ty * 8 + 4]);
            *reinterpret_cast<float4*>(&br[0]) =
                *reinterpret_cast<const float4*>(&Bs[kk][tx * 8]);
            *reinterpret_cast<float4*>(&br[4]) =
                *reinterpret_cast<const float4*>(&Bs[kk][tx * 8 + 4]);
            #pragma unroll
            for (int i = 0; i < 8; i++)
                #pragma unroll
                for (int j = 0; j < 8; j++)
                    acc[i][j] = fmaf(ar[i], br[j], acc[i][j]);
        }
    }

    // epilogue into S (the inputs scratch region)
    #pragma unroll
    for (int i = 0; i < 8; i++) {
        float* crow = S + (size_t)(bm + ty * 8 + i) * N_ + bn + tx * 8;
        *reinterpret_cast<float4*>(crow) =
            make_float4(acc[i][0], acc[i][1], acc[i][2], acc[i][3]);
        *reinterpret_cast<float4*>(crow + 4) =
            make_float4(acc[i][4], acc[i][5], acc[i][6], acc[i][7]);
    }

    // ================= publish + maybe-scan ================================
    // A 128-row m-tile touches 1 or 2 batches (T_=500 not a multiple of 128).
    __shared__ int do_scan[2];
    __threadfence();                // make C stores visible device-wide
    __syncthreads();                // all stores in this block done
    if (tid == 0) {
        do_scan[0] = -1; do_scan[1] = -1;
        const int b_lo = bm / T_;
        const int b_hi = (bm + 127) / T_;
        int slot = 0;
        for (int b = b_lo; b <= b_hi; b++) {
            const int my_lo = (b * T_) >> 7;
            const int my_hi = (b * T_ + T_ - 1) >> 7;
            const int target = (my_hi - my_lo + 1) * 8;   // tiles covering batch b
            if (atomicAdd(&g_cnt[b], 1) == target - 1)
                do_scan[slot++] = b;                      // we're the last tile
        }
    }
    __syncthreads();

    #pragma unroll
    for (int s = 0; s < 2; s++) {
        const int b = do_scan[s];
        if (b >= 0) {
            __threadfence();        // acquire: see all tiles' C stores
            scan_batch(b, tid, U, S);
        }
    }
}

// ---------------------------------------------------------------------------
extern "C" void kernel_launch(void* const* d_in, const int* in_sizes, int n_in,
                              void* d_out, int out_size) {
    const float* X = (const float*)d_in[0];   // [128, 500, 700]
    const float* W = (const float*)d_in[1];   // [1024, 700]
    float* outU = (float*)d_out;              // [128, 500, 1024]
    float* outS = outU + (size_t)M_ * N_;     // [128, 500, 1024]

    zero_cnt_kernel<<<1, 128>>>();
    fused_kernel<<<GEMM_BLOCKS, 256>>>(X, W, outU, outS);
}

// round 16
// speedup vs baseline: 1.1400x; 1.0111x over previous
#include <cuda_runtime.h>
#include <cuda_bf16.h>
#include <cstdint>

// SpikingLayer: inputs = X @ W^T, then LIF scan — fused; the last GEMM tile
// per batch runs that batch's scan (R15 WIN: overlap costs zero slots).
//
// Constraints learned:
//  R6/R7: LIF threshold demands the reference's sequential-k fp32 FMA chain
//         bitwise (any reorder -> spike flips -> rel_err ~1.3e-3 FAIL).
//  R2/R15: sequential SIMT fp32 GEMM = rel_err 0.0; R15 = 2427us, ~95% of the
//         FFMA issue floor (fma pipe 47.7% of ~50% ceiling).
//  R11:   FFMA2 is not a FLOP doubler. Tensor cores are bitwise-incompatible.
//  => this round attacks the remaining ~5% barrier/latency bubbles:
//     BK=16 (half the barriers), double-buffered smem, LDG prefetch ahead of
//     compute. Arithmetic chain order is UNCHANGED -> bitwise identical.
//
// d_out = U [128,500,1024] ++ S [128,500,1024] (S region doubles as GEMM scratch).

static constexpr int M_ = 64000;   // 128*500
static constexpr int N_ = 1024;
static constexpr int K_ = 700;
static constexpr int B_ = 128;
static constexpr int T_ = 500;
static constexpr int H_ = 1024;

static constexpr int BK = 16;
static constexpr int NCH = (K_ + BK - 1) / BK;   // 44 (last chunk zero-padded)

static constexpr int GEMM_BLOCKS = (M_ / 128) * (N_ / 128);  // 4000

__device__ int g_cnt[B_];   // per-batch GEMM-tile completion counters

__global__ void zero_cnt_kernel() {
    if (threadIdx.x < B_) g_cnt[threadIdx.x] = 0;
}

// ---------------------------------------------------------------------------
// LIF scan for one batch, run by one 256-thread block: 4 neurons per thread
// (float4), in-place over the S region (read-ahead by 7 -> WAR safe).
// ---------------------------------------------------------------------------
__device__ __forceinline__ void scan_batch(int b, int tid, float* U, float* S) {
    const float PHI = 0.36787944117144233f;   // exp(-1)
    const float GAM = 0.81873075307798182f;   // exp(-0.2)
    const float BET = 0.90483741803595952f;   // exp(-0.1)
    const int P4 = H_ / 4;                    // 256 float4 per (b,t)

    float4* Up = reinterpret_cast<float4*>(U) + (size_t)b * T_ * P4 + tid;
    float4* Sp = reinterpret_cast<float4*>(S) + (size_t)b * T_ * P4 + tid;

    float4 buf[8];
    #pragma unroll
    for (int i = 0; i < 8; i++) buf[i] = Sp[(size_t)i * P4];

    Up[0] = make_float4(0.f, 0.f, 0.f, 0.f);
    Sp[0] = make_float4(0.f, 0.f, 0.f, 0.f);

    float Hs[4] = {0.f, 0.f, 0.f, 0.f};
    float Is[4] = {0.f, 0.f, 0.f, 0.f};
    float Us[4] = {0.f, 0.f, 0.f, 0.f};
    float Ss[4] = {0.f, 0.f, 0.f, 0.f};

    for (int t0 = 1; t0 < T_; t0 += 8) {
        #pragma unroll
        for (int u = 0; u < 8; u++) {
            const int t = t0 + u;
            if (t < T_) {
                const float4 inp = buf[u];                         // inputs[t-1]
                if (t + 7 < T_) buf[u] = Sp[(size_t)(t + 7) * P4]; // prefetch
                const float in_[4] = {inp.x, inp.y, inp.z, inp.w};
                float Un[4], Sn[4];
                #pragma unroll
                for (int q = 0; q < 4; q++) {
                    const float Hn = fmaf(PHI, Hs[q], in_[q]);
                    const float In = fmaf(GAM, Is[q], Hs[q]);
                    Un[q] = BET * (Us[q] - Is[q]) - Ss[q];
                    Sn[q] = (Un[q] > 1.f) ? 1.f : 0.f;
                    Hs[q] = Hn; Is[q] = In; Us[q] = Un[q]; Ss[q] = Sn[q];
                }
                Up[(size_t)t * P4] = make_float4(Un[0], Un[1], Un[2], Un[3]);
                Sp[(size_t)t * P4] = make_float4(Sn[0], Sn[1], Sn[2], Sn[3]);
            }
        }
    }
}

// ---------------------------------------------------------------------------
// Fused kernel: BK=16 double-buffered GEMM; last tile per batch scans it.
// ---------------------------------------------------------------------------
__global__ void __launch_bounds__(256, 2) fused_kernel(
    const float* __restrict__ A,   // X  [M_, K_]
    const float* __restrict__ W,   // W  [N_, K_]
    float* __restrict__ U,         // [B_, T_, H_]
    float* S)                      // [B_, T_, H_] : GEMM C output, then spikes in-place
{
    const int id = blockIdx.x;
    const int tid = threadIdx.x;

    __shared__ float As[2][BK][128];   // 16KB
    __shared__ float Bs[2][BK][128];   // 16KB

    const int my = id >> 3;          // 0..499
    const int nx = id & 7;           // 0..7
    const int bm = my * 128;
    const int bn = nx * 128;

    // global-load mapping: 256 threads cover 128 rows x 16 k (2 float4 each)
    const int lr = tid >> 1;         // 0..127
    const int lk = (tid & 1) * 8;    // 0 or 8
    const float* Aptr = A + (size_t)(bm + lr) * K_ + lk;
    const float* Wptr = W + (size_t)(bn + lr) * K_ + lk;

    const int ty = tid >> 4;         // rows ty*8..ty*8+7
    const int tx = tid & 15;         // cols tx*8..tx*8+7

    float acc[8][8];
    #pragma unroll
    for (int i = 0; i < 8; i++)
        #pragma unroll
        for (int j = 0; j < 8; j++) acc[i][j] = 0.0f;

    const float4 fz = make_float4(0.f, 0.f, 0.f, 0.f);

    // chunk loader (guards only bite in chunk 43: k=700..703 zero)
    auto ldg_chunk = [&](int j, float4& a0, float4& a1, float4& b0, float4& b1) {
        const int k0 = j * BK;
        a0 = fz; a1 = fz; b0 = fz; b1 = fz;
        if (k0 + lk + 4 <= K_) {
            a0 = *reinterpret_cast<const float4*>(Aptr + k0);
            b0 = *reinterpret_cast<const float4*>(Wptr + k0);
        }
        if (k0 + lk + 8 <= K_) {
            a1 = *reinterpret_cast<const float4*>(Aptr + k0 + 4);
            b1 = *reinterpret_cast<const float4*>(Wptr + k0 + 4);
        }
    };
    auto sts_chunk = [&](int s, const float4& a0, const float4& a1,
                         const float4& b0, const float4& b1) {
        As[s][lk + 0][lr] = a0.x; As[s][lk + 1][lr] = a0.y;
        As[s][lk + 2][lr] = a0.z; As[s][lk + 3][lr] = a0.w;
        As[s][lk + 4][lr] = a1.x; As[s][lk + 5][lr] = a1.y;
        As[s][lk + 6][lr] = a1.z; As[s][lk + 7][lr] = a1.w;
        Bs[s][lk + 0][lr] = b0.x; Bs[s][lk + 1][lr] = b0.y;
        Bs[s][lk + 2][lr] = b0.z; Bs[s][lk + 3][lr] = b0.w;
        Bs[s][lk + 4][lr] = b1.x; Bs[s][lk + 5][lr] = b1.y;
        Bs[s][lk + 6][lr] = b1.z; Bs[s][lk + 7][lr] = b1.w;
    };

    {   // prologue: stage 0
        float4 a0, a1, b0, b1;
        ldg_chunk(0, a0, a1, b0, b1);
        sts_chunk(0, a0, a1, b0, b1);
    }

    for (int j = 0; j < NCH; j++) {
        // prefetch next chunk into registers (overlaps with compute below)
        float4 na0, na1, nb0, nb1;
        if (j + 1 < NCH) ldg_chunk(j + 1, na0, na1, nb0, nb1);

        __syncthreads();              // stage j%2 fully stored
        const int s = j & 1;
        #pragma unroll
        for (int kk = 0; kk < BK; kk++) {
            float ar[8], br[8];
            *reinterpret_cast<float4*>(&ar[0]) =
                *reinterpret_cast<const float4*>(&As[s][kk][ty * 8]);
            *reinterpret_cast<float4*>(&ar[4]) =
                *reinterpret_cast<const float4*>(&As[s][kk][ty * 8 + 4]);
            *reinterpret_cast<float4*>(&br[0]) =
                *reinterpret_cast<const float4*>(&Bs[s][kk][tx * 8]);
            *reinterpret_cast<float4*>(&br[4]) =
                *reinterpret_cast<const float4*>(&Bs[s][kk][tx * 8 + 4]);
            #pragma unroll
            for (int i = 0; i < 8; i++)
                #pragma unroll
                for (int jj = 0; jj < 8; jj++)
                    acc[i][jj] = fmaf(ar[i], br[jj], acc[i][jj]);
        }
        __syncthreads();              // everyone done reading stage j%2
        if (j + 1 < NCH) sts_chunk((j + 1) & 1, na0, na1, nb0, nb1);
    }

    // epilogue into S (the inputs scratch region)
    #pragma unroll
    for (int i = 0; i < 8; i++) {
        float* crow = S + (size_t)(bm + ty * 8 + i) * N_ + bn + tx * 8;
        *reinterpret_cast<float4*>(crow) =
            make_float4(acc[i][0], acc[i][1], acc[i][2], acc[i][3]);
        *reinterpret_cast<float4*>(crow + 4) =
            make_float4(acc[i][4], acc[i][5], acc[i][6], acc[i][7]);
    }

    // ================= publish + maybe-scan ================================
    __shared__ int do_scan[2];
    __threadfence();                // make C stores visible device-wide
    __syncthreads();                // all stores in this block done
    if (tid == 0) {
        do_scan[0] = -1; do_scan[1] = -1;
        const int b_lo = bm / T_;
        const int b_hi = (bm + 127) / T_;
        int slot = 0;
        for (int b = b_lo; b <= b_hi; b++) {
            const int my_lo = (b * T_) >> 7;
            const int my_hi = (b * T_ + T_ - 1) >> 7;
            const int target = (my_hi - my_lo + 1) * 8;   // tiles covering batch b
            if (atomicAdd(&g_cnt[b], 1) == target - 1)
                do_scan[slot++] = b;                      // we're the last tile
        }
    }
    __syncthreads();

    #pragma unroll
    for (int s2 = 0; s2 < 2; s2++) {
        const int b = do_scan[s2];
        if (b >= 0) {
            __threadfence();        // acquire: see all tiles' C stores
            scan_batch(b, tid, U, S);
        }
    }
}

// ---------------------------------------------------------------------------
extern "C" void kernel_launch(void* const* d_in, const int* in_sizes, int n_in,
                              void* d_out, int out_size) {
    const float* X = (const float*)d_in[0];   // [128, 500, 700]
    const float* W = (const float*)d_in[1];   // [1024, 700]
    float* outU = (float*)d_out;              // [128, 500, 1024]
    float* outS = outU + (size_t)M_ * N_;     // [128, 500, 1024]

    zero_cnt_kernel<<<1, 128>>>();
    fused_kernel<<<GEMM_BLOCKS, 256>>>(X, W, outU, outS);
}

// round 17
// speedup vs baseline: 1.1670x; 1.0237x over previous
#include <cuda_runtime.h>
#include <cuda_bf16.h>
#include <cstdint>

// SpikingLayer: inputs = X @ W^T, then LIF scan — fused, persistent-CTA.
//
// Constraints learned:
//  R6/R7: LIF threshold demands the reference's sequential-k fp32 FMA chain
//         bitwise (any reorder -> spike flips -> rel_err ~1.3e-3 FAIL).
//  R2..R16: sequential SIMT fp32 GEMM at the FFMA issue floor; R16 = 2400us
//         (BK=16 double-buffered, fma pipe 51.1%). Tensor cores / FFMA2 are
//         dead ends. Scan hidden via last-tile trigger (R15).
//  R16 residual ~90us = wave quantization (4000 blocks / 296 resident = 13.51
//         waves -> half-idle final wave).
//  => this round: persistent blocks (2/SM) + dynamic tile queue. Tile math is
//     byte-identical; only the scheduler changes.
//
// d_out = U [128,500,1024] ++ S [128,500,1024] (S region doubles as GEMM scratch).

static constexpr int M_ = 64000;   // 128*500
static constexpr int N_ = 1024;
static constexpr int K_ = 700;
static constexpr int B_ = 128;
static constexpr int T_ = 500;
static constexpr int H_ = 1024;

static constexpr int BK = 16;
static constexpr int NCH = (K_ + BK - 1) / BK;   // 44 (last chunk zero-padded)

static constexpr int GEMM_TILES = (M_ / 128) * (N_ / 128);  // 4000

__device__ int g_cnt[B_];   // per-batch GEMM-tile completion counters
__device__ int g_work;      // dynamic tile queue head

__global__ void zero_cnt_kernel() {
    if (threadIdx.x < B_) g_cnt[threadIdx.x] = 0;
    if (threadIdx.x == 0) g_work = 0;
}

// ---------------------------------------------------------------------------
// LIF scan for one batch, run by one 256-thread block: 4 neurons per thread
// (float4), in-place over the S region (read-ahead by 7 -> WAR safe).
// ---------------------------------------------------------------------------
__device__ __forceinline__ void scan_batch(int b, int tid, float* U, float* S) {
    const float PHI = 0.36787944117144233f;   // exp(-1)
    const float GAM = 0.81873075307798182f;   // exp(-0.2)
    const float BET = 0.90483741803595952f;   // exp(-0.1)
    const int P4 = H_ / 4;                    // 256 float4 per (b,t)

    float4* Up = reinterpret_cast<float4*>(U) + (size_t)b * T_ * P4 + tid;
    float4* Sp = reinterpret_cast<float4*>(S) + (size_t)b * T_ * P4 + tid;

    float4 buf[8];
    #pragma unroll
    for (int i = 0; i < 8; i++) buf[i] = Sp[(size_t)i * P4];

    Up[0] = make_float4(0.f, 0.f, 0.f, 0.f);
    Sp[0] = make_float4(0.f, 0.f, 0.f, 0.f);

    float Hs[4] = {0.f, 0.f, 0.f, 0.f};
    float Is[4] = {0.f, 0.f, 0.f, 0.f};
    float Us[4] = {0.f, 0.f, 0.f, 0.f};
    float Ss[4] = {0.f, 0.f, 0.f, 0.f};

    for (int t0 = 1; t0 < T_; t0 += 8) {
        #pragma unroll
        for (int u = 0; u < 8; u++) {
            const int t = t0 + u;
            if (t < T_) {
                const float4 inp = buf[u];                         // inputs[t-1]
                if (t + 7 < T_) buf[u] = Sp[(size_t)(t + 7) * P4]; // prefetch
                const float in_[4] = {inp.x, inp.y, inp.z, inp.w};
                float Un[4], Sn[4];
                #pragma unroll
                for (int q = 0; q < 4; q++) {
                    const float Hn = fmaf(PHI, Hs[q], in_[q]);
                    const float In = fmaf(GAM, Is[q], Hs[q]);
                    Un[q] = BET * (Us[q] - Is[q]) - Ss[q];
                    Sn[q] = (Un[q] > 1.f) ? 1.f : 0.f;
                    Hs[q] = Hn; Is[q] = In; Us[q] = Un[q]; Ss[q] = Sn[q];
                }
                Up[(size_t)t * P4] = make_float4(Un[0], Un[1], Un[2], Un[3]);
                Sp[(size_t)t * P4] = make_float4(Sn[0], Sn[1], Sn[2], Sn[3]);
            }
        }
    }
}

// ---------------------------------------------------------------------------
// Persistent fused kernel: pop tiles from a queue; BK=16 double-buffered GEMM;
// the tile that completes a batch scans it (others keep popping -> auto-balance).
// ---------------------------------------------------------------------------
__global__ void __launch_bounds__(256, 2) fused_kernel(
    const float* __restrict__ A,   // X  [M_, K_]
    const float* __restrict__ W,   // W  [N_, K_]
    float* __restrict__ U,         // [B_, T_, H_]
    float* S)                      // [B_, T_, H_] : GEMM C output, then spikes in-place
{
    const int tid = threadIdx.x;

    __shared__ float As[2][BK][128];   // 16KB
    __shared__ float Bs[2][BK][128];   // 16KB
    __shared__ int sh_tile;
    __shared__ int do_scan[2];

    const int lr = tid >> 1;         // 0..127
    const int lk = (tid & 1) * 8;    // 0 or 8
    const int ty = tid >> 4;         // rows ty*8..ty*8+7
    const int tx = tid & 15;         // cols tx*8..tx*8+7
    const float4 fz = make_float4(0.f, 0.f, 0.f, 0.f);

    for (;;) {
        // ---- pop next tile ----
        if (tid == 0) sh_tile = atomicAdd(&g_work, 1);
        __syncthreads();
        const int id = sh_tile;
        if (id >= GEMM_TILES) return;

        const int my = id >> 3;          // 0..499
        const int nx = id & 7;           // 0..7
        const int bm = my * 128;
        const int bn = nx * 128;

        const float* Aptr = A + (size_t)(bm + lr) * K_ + lk;
        const float* Wptr = W + (size_t)(bn + lr) * K_ + lk;

        float acc[8][8];
        #pragma unroll
        for (int i = 0; i < 8; i++)
            #pragma unroll
            for (int j = 0; j < 8; j++) acc[i][j] = 0.0f;

        auto ldg_chunk = [&](int j, float4& a0, float4& a1, float4& b0, float4& b1) {
            const int k0 = j * BK;
            a0 = fz; a1 = fz; b0 = fz; b1 = fz;
            if (k0 + lk + 4 <= K_) {
                a0 = *reinterpret_cast<const float4*>(Aptr + k0);
                b0 = *reinterpret_cast<const float4*>(Wptr + k0);
            }
            if (k0 + lk + 8 <= K_) {
                a1 = *reinterpret_cast<const float4*>(Aptr + k0 + 4);
                b1 = *reinterpret_cast<const float4*>(Wptr + k0 + 4);
            }
        };
        auto sts_chunk = [&](int s, const float4& a0, const float4& a1,
                             const float4& b0, const float4& b1) {
            As[s][lk + 0][lr] = a0.x; As[s][lk + 1][lr] = a0.y;
            As[s][lk + 2][lr] = a0.z; As[s][lk + 3][lr] = a0.w;
            As[s][lk + 4][lr] = a1.x; As[s][lk + 5][lr] = a1.y;
            As[s][lk + 6][lr] = a1.z; As[s][lk + 7][lr] = a1.w;
            Bs[s][lk + 0][lr] = b0.x; Bs[s][lk + 1][lr] = b0.y;
            Bs[s][lk + 2][lr] = b0.z; Bs[s][lk + 3][lr] = b0.w;
            Bs[s][lk + 4][lr] = b1.x; Bs[s][lk + 5][lr] = b1.y;
            Bs[s][lk + 6][lr] = b1.z; Bs[s][lk + 7][lr] = b1.w;
        };

        {   // prologue: stage 0 (previous tile's readers are past: popped after
            // a __syncthreads that follows their last smem read)
            float4 a0, a1, b0, b1;
            ldg_chunk(0, a0, a1, b0, b1);
            sts_chunk(0, a0, a1, b0, b1);
        }

        for (int j = 0; j < NCH; j++) {
            float4 na0, na1, nb0, nb1;
            if (j + 1 < NCH) ldg_chunk(j + 1, na0, na1, nb0, nb1);

            __syncthreads();              // stage j%2 fully stored
            const int s = j & 1;
            #pragma unroll
            for (int kk = 0; kk < BK; kk++) {
                float ar[8], br[8];
                *reinterpret_cast<float4*>(&ar[0]) =
                    *reinterpret_cast<const float4*>(&As[s][kk][ty * 8]);
                *reinterpret_cast<float4*>(&ar[4]) =
                    *reinterpret_cast<const float4*>(&As[s][kk][ty * 8 + 4]);
                *reinterpret_cast<float4*>(&br[0]) =
                    *reinterpret_cast<const float4*>(&Bs[s][kk][tx * 8]);
                *reinterpret_cast<float4*>(&br[4]) =
                    *reinterpret_cast<const float4*>(&Bs[s][kk][tx * 8 + 4]);
                #pragma unroll
                for (int i = 0; i < 8; i++)
                    #pragma unroll
                    for (int jj = 0; jj < 8; jj++)
                        acc[i][jj] = fmaf(ar[i], br[jj], acc[i][jj]);
            }
            __syncthreads();              // everyone done reading stage j%2
            if (j + 1 < NCH) sts_chunk((j + 1) & 1, na0, na1, nb0, nb1);
        }

        // epilogue into S (the inputs scratch region)
        #pragma unroll
        for (int i = 0; i < 8; i++) {
            float* crow = S + (size_t)(bm + ty * 8 + i) * N_ + bn + tx * 8;
            *reinterpret_cast<float4*>(crow) =
                make_float4(acc[i][0], acc[i][1], acc[i][2], acc[i][3]);
            *reinterpret_cast<float4*>(crow + 4) =
                make_float4(acc[i][4], acc[i][5], acc[i][6], acc[i][7]);
        }

        // ---- publish + maybe-scan ----
        __threadfence();                // make C stores visible device-wide
        __syncthreads();                // all stores in this block done
        if (tid == 0) {
            do_scan[0] = -1; do_scan[1] = -1;
            const int b_lo = bm / T_;
            const int b_hi = (bm + 127) / T_;
            int slot = 0;
            for (int b = b_lo; b <= b_hi; b++) {
                const int my_lo = (b * T_) >> 7;
                const int my_hi = (b * T_ + T_ - 1) >> 7;
                const int target = (my_hi - my_lo + 1) * 8;   // tiles covering b
                if (atomicAdd(&g_cnt[b], 1) == target - 1)
                    do_scan[slot++] = b;                      // last tile of b
            }
        }
        __syncthreads();

        #pragma unroll
        for (int s2 = 0; s2 < 2; s2++) {
            const int b = do_scan[s2];
            if (b >= 0) {
                __threadfence();        // acquire: see all tiles' C stores
                scan_batch(b, tid, U, S);
            }
        }
        __syncthreads();                // scan readers done before next tile's STS
    }
}

// ---------------------------------------------------------------------------
extern "C" void kernel_launch(void* const* d_in, const int* in_sizes, int n_in,
                              void* d_out, int out_size) {
    const float* X = (const float*)d_in[0];   // [128, 500, 700]
    const float* W = (const float*)d_in[1];   // [1024, 700]
    float* outU = (float*)d_out;              // [128, 500, 1024]
    float* outS = outU + (size_t)M_ * N_;     // [128, 500, 1024]

    int dev = 0, nsm = 148;
    cudaGetDevice(&dev);
    cudaDeviceGetAttribute(&nsm, cudaDevAttrMultiProcessorCount, dev);

    zero_cnt_kernel<<<1, 128>>>();
    fused_kernel<<<2 * nsm, 256>>>(X, W, outU, outS);
}